// round 12
// baseline (speedup 1.0000x reference)
#include <cuda_runtime.h>

#define BATCH 32
#define NCH   4
#define HH    512
#define WW    512
#define PLANE (HH*WW)          /* 262144 */
#define NSTEPS 8
#define D_SCALE 0.2f
#define RHO_SCALE 0.1f
#define FULLM 0xffffffffu

#define SBX 32                  /* stencil blocks in x */
#define CBX 24                  /* copy blocks in x (per batch, per kernel) */
/* ch1-3 of one batch = 3*PLANE floats = 196608 float4; quarter = 49152;
   per copy block = 49152/24 = 2048 float4 = 256 thr x 8 */

// Ping-pong scratch for the evolving channel-0 field (2 x 32 MiB).
__device__ float g_buf0[BATCH * PLANE];
__device__ float g_buf1[BATCH * PLANE];
// Sums at even steps 0,2,4,6,8: slot k = state entering fused kernel k.
__device__ float g_sum0[5 * BATCH];
__device__ float g_sumsq[5 * BATCH];
// Constant sums of channels 1..3 (index (c-1)*BATCH + b).
__device__ float g_sumc[3 * BATCH];

__global__ void zero_sums_kernel() {
    int i = threadIdx.x;
    if (i < 5 * BATCH) { g_sum0[i] = 0.0f; g_sumsq[i] = 0.0f; }
    if (i < 3 * BATCH) g_sumc[i] = 0.0f;
}

// Reduce all per-(batch,channel) sums (+ sumsq for ch0). NO copying.
// grid = (PLANE/4/256, BATCH*NCH), block = 256.
__global__ void sums_kernel(const float* __restrict__ x) {
    const int p = blockIdx.y;            // plane id = b*4 + c
    const int b = p >> 2;
    const int c = p & 3;
    const int i = blockIdx.x * blockDim.x + threadIdx.x;

    const float4 v = ((const float4*)(x + (size_t)p * PLANE))[i];
    float s  = (v.x + v.y) + (v.z + v.w);
    float s2 = (v.x * v.x + v.y * v.y) + (v.z * v.z + v.w * v.w);

    #pragma unroll
    for (int o = 16; o > 0; o >>= 1) {
        s  += __shfl_down_sync(FULLM, s,  o);
        s2 += __shfl_down_sync(FULLM, s2, o);
    }
    __shared__ float ws[8], ws2[8];
    const int lane = threadIdx.x & 31;
    const int w    = threadIdx.x >> 5;
    if (lane == 0) { ws[w] = s; ws2[w] = s2; }
    __syncthreads();
    if (w == 0) {
        s  = (lane < 8) ? ws[lane]  : 0.0f;
        s2 = (lane < 8) ? ws2[lane] : 0.0f;
        #pragma unroll
        for (int o = 4; o > 0; o >>= 1) {
            s  += __shfl_down_sync(0x000000ffu, s,  o);
            s2 += __shfl_down_sync(0x000000ffu, s2, o);
        }
        if (lane == 0) {
            if (c == 0) {
                atomicAdd(&g_sum0[b],  s);
                atomicAdd(&g_sumsq[b], s2);
            } else {
                atomicAdd(&g_sumc[(c - 1) * BATCH + b], s);
            }
        }
    }
}

// TWO fused reaction-diffusion steps (warp-private) + embedded ch1-3 copy.
//   sum_{s+1} = sum_s + rho_s*(sum_s - sumsq_s)   (periodic: sum(lap)=0)
// blockIdx.x <  SBX : stencil block (as R10: warp = chunk x 8-row strip,
//                     pipelined loads, regs<=64).
// blockIdx.x >= SBX : copy block — copies quarter `slot` of batch b's ch1-3
//                     from x to out (2048 float4), soaking idle DRAM BW.
// grid = (SBX+CBX, BATCH), block = 256.
__global__ __launch_bounds__(256, 4) void fused2_kernel(
        const float* __restrict__ src, int src_bstride,
        float* __restrict__ dst, int dst_bstride,
        const float* __restrict__ xin, float* __restrict__ outp,
        const float* __restrict__ Wm,
        const float* __restrict__ bias,
        const int* __restrict__ t, int s) {
    const int b    = blockIdx.y;
    const int tid  = threadIdx.x;
    const int slot = s >> 1;

    // ---------------- Copy block path ----------------
    if (blockIdx.x >= SBX) {
        const int cb = blockIdx.x - SBX;                 // 0..23
        const size_t base = ((size_t)(b * NCH + 1) * PLANE) >> 2;  // float4 idx
        const size_t off  = base + (size_t)slot * 49152 + (size_t)cb * 2048 + tid;
        const float4* __restrict__ sp = (const float4*)xin + off;
        float4* __restrict__ dp       = (float4*)outp + off;
        #pragma unroll
        for (int j = 0; j < 8; j++)
            dp[j * 256] = sp[j * 256];
        return;
    }

    // ---------------- Stencil path (R10 engine) ----------------
    const int lane = tid & 31;
    const int wid  = tid >> 5;
    const int chunk = wid & 3;
    const int grp   = wid >> 2;                 // 0 or 1
    const int y0    = blockIdx.x * 16 + grp * 8;

    const float* __restrict__ u = src + (size_t)b * src_bstride;
    float* __restrict__ v       = dst + (size_t)b * dst_bstride;

    const int xb  = chunk << 7;
    const int x4  = xb + (lane << 2);
    const int xl2 = (xb + WW - 2) & (WW - 1);   // cols xb-2, xb-1 (float2)
    const int xr2 = (xb + 128) & (WW - 1);      // cols xb+128, xb+129 (float2)

    // ---- Edge data for 12 rows (lanes 0..11), issued first ----
    float2 eL = make_float2(0.f, 0.f), eR = make_float2(0.f, 0.f);
    float sxb = 0.0f, sxbr = 0.0f;
    if (lane < 12) {
        const int row = ((y0 - 2 + lane) & (HH - 1)) << 9;
        eL   = *(const float2*)(u + row + xl2);   // (xb-2, xb-1)
        eR   = *(const float2*)(u + row + xr2);   // (xb+128, xb+129)
        sxb  = u[row + xb];                       // col xb
        sxbr = u[row + xb + 127];                 // col xb+127
    }

    // ---- Software-pipelined main-row loads: preload 5 of 12 ----
    float4 R[12];
    #pragma unroll
    for (int k = 0; k < 5; k++)
        R[k] = *(const float4*)(u + (((y0 - 2 + k) & (HH - 1)) << 9) + x4);

    // ---- D/rho for both sub-steps (overlaps loads) ----
    const float inv = 1.0f / (float)PLANE;
    const float sum_s = g_sum0[slot * BATCH + b];
    const float ssq_s = g_sumsq[slot * BATCH + b];
    const float f1 = g_sumc[0 * BATCH + b] * inv;
    const float f2 = g_sumc[1 * BATCH + b] * inv;
    const float f3 = g_sumc[2 * BATCH + b] * inv;
    const float zc0 = f1 * Wm[2] + f2 * Wm[4] + f3 * Wm[6] + bias[0];
    const float zc1 = f1 * Wm[3] + f2 * Wm[5] + f3 * Wm[7] + bias[1];
    const int tb = t[b];

    const float f0 = sum_s * inv;
    float D0 = D_SCALE   / (1.0f + __expf(-(f0 * Wm[0] + zc0)));
    float r0 = RHO_SCALE / (1.0f + __expf(-(f0 * Wm[1] + zc1)));
    if (tb <= s) { D0 = 0.0f; r0 = 0.0f; }

    const float sum_n = sum_s + r0 * (sum_s - ssq_s);   // exact (periodic BC)
    const float f0n = sum_n * inv;
    float D1 = D_SCALE   / (1.0f + __expf(-(f0n * Wm[0] + zc0)));
    float r1 = RHO_SCALE / (1.0f + __expf(-(f0n * Wm[1] + zc1)));
    if (tb <= s + 1) { D1 = 0.0f; r1 = 0.0f; }

    // ---- Edge intermediates: lane i = row y0-2+i (valid i=1..10) ----
    float iLv, iRv;
    {
        float up = __shfl_up_sync(FULLM, eL.y, 1);
        float dn = __shfl_down_sync(FULLM, eL.y, 1);
        iLv = fmaf(D0, up + dn + eL.x + sxb - 4.0f * eL.y,
                   fmaf(r0 * eL.y, 1.0f - eL.y, eL.y));
        up = __shfl_up_sync(FULLM, eR.x, 1);
        dn = __shfl_down_sync(FULLM, eR.x, 1);
        iRv = fmaf(D0, up + dn + sxbr + eR.y - 4.0f * eR.x,
                   fmaf(r0 * eR.x, 1.0f - eR.x, eR.x));
    }

    // ---- Main loop: intermediates m=0..9 (rows y0-1..y0+8), outputs j=m-2 ----
    float4 I[3];
    float acc = 0.0f, acc2 = 0.0f;
    #pragma unroll
    for (int m = 0; m < 10; m++) {
        if (m + 5 < 12)
            R[m + 5] = *(const float4*)(u + (((y0 + 3 + m) & (HH - 1)) << 9) + x4);

        const float4 P = R[m], C = R[m + 1], N = R[m + 2];
        const float lein = __shfl_sync(FULLM, eL.y, m + 1);
        const float riin = __shfl_sync(FULLM, eR.x, m + 1);
        float le = __shfl_up_sync(FULLM, C.w, 1);
        float ri = __shfl_down_sync(FULLM, C.x, 1);
        if (lane == 0)  le = lein;
        if (lane == 31) ri = riin;

        float4 o;
        o.x = fmaf(D0, P.x + N.x + le  + C.y - 4.0f * C.x, fmaf(r0 * C.x, 1.0f - C.x, C.x));
        o.y = fmaf(D0, P.y + N.y + C.x + C.z - 4.0f * C.y, fmaf(r0 * C.y, 1.0f - C.y, C.y));
        o.z = fmaf(D0, P.z + N.z + C.y + C.w - 4.0f * C.z, fmaf(r0 * C.z, 1.0f - C.z, C.z));
        o.w = fmaf(D0, P.w + N.w + C.z + ri  - 4.0f * C.w, fmaf(r0 * C.w, 1.0f - C.w, C.w));
        I[m % 3] = o;

        if (m >= 2) {
            const int j = m - 2;                      // output row y0+j
            const float4 Pm = I[j % 3];
            const float4 Cm = I[(j + 1) % 3];
            const float4 Nm = I[(j + 2) % 3];
            const float leo = __shfl_sync(FULLM, iLv, j + 2);
            const float rio = __shfl_sync(FULLM, iRv, j + 2);
            float le2 = __shfl_up_sync(FULLM, Cm.w, 1);
            float ri2 = __shfl_down_sync(FULLM, Cm.x, 1);
            if (lane == 0)  le2 = leo;
            if (lane == 31) ri2 = rio;

            float4 q;
            q.x = fmaf(D1, Pm.x + Nm.x + le2 + Cm.y - 4.0f * Cm.x, fmaf(r1 * Cm.x, 1.0f - Cm.x, Cm.x));
            q.y = fmaf(D1, Pm.y + Nm.y + Cm.x + Cm.z - 4.0f * Cm.y, fmaf(r1 * Cm.y, 1.0f - Cm.y, Cm.y));
            q.z = fmaf(D1, Pm.z + Nm.z + Cm.y + Cm.w - 4.0f * Cm.z, fmaf(r1 * Cm.z, 1.0f - Cm.z, Cm.z));
            q.w = fmaf(D1, Pm.w + Nm.w + Cm.z + ri2  - 4.0f * Cm.w, fmaf(r1 * Cm.w, 1.0f - Cm.w, Cm.w));

            *(float4*)(v + ((y0 + j) << 9) + x4) = q;
            acc  += (q.x + q.y) + (q.z + q.w);
            acc2 += (q.x * q.x + q.y * q.y) + (q.z * q.z + q.w * q.w);
        }
    }

    // ---- Block reduction of sum & sumsq, one atomic pair per block ----
    #pragma unroll
    for (int o = 16; o > 0; o >>= 1) {
        acc  += __shfl_down_sync(FULLM, acc,  o);
        acc2 += __shfl_down_sync(FULLM, acc2, o);
    }
    __shared__ float ws[8], ws2[8];
    if (lane == 0) { ws[wid] = acc; ws2[wid] = acc2; }
    __syncthreads();
    if (wid == 0) {
        acc  = (lane < 8) ? ws[lane]  : 0.0f;
        acc2 = (lane < 8) ? ws2[lane] : 0.0f;
        #pragma unroll
        for (int o = 4; o > 0; o >>= 1) {
            acc  += __shfl_down_sync(0x000000ffu, acc,  o);
            acc2 += __shfl_down_sync(0x000000ffu, acc2, o);
        }
        if (lane == 0) {
            atomicAdd(&g_sum0[(slot + 1) * BATCH + b],  acc);
            atomicAdd(&g_sumsq[(slot + 1) * BATCH + b], acc2);
        }
    }
}

extern "C" void kernel_launch(void* const* d_in, const int* in_sizes, int n_in,
                              void* d_out, int out_size) {
    const float* x  = (const float*)d_in[0];   // (32,4,512,512)
    const float* Wm = (const float*)d_in[1];   // (4,2)
    const float* bb = (const float*)d_in[2];   // (2,)
    const int*   t  = (const int*)d_in[3];     // (32,)
    float* out = (float*)d_out;

    zero_sums_kernel<<<1, 256>>>();

    // All per-(b,c) sums (+ sumsq ch0); read-only pass.
    sums_kernel<<<dim3(PLANE / 4 / 256, BATCH * NCH), dim3(256)>>>(x);

    float* bufA; float* bufB;
    cudaGetSymbolAddress((void**)&bufA, g_buf0);
    cudaGetSymbolAddress((void**)&bufB, g_buf1);

    const dim3 fgrid(SBX + CBX, BATCH);   // 56 x 32 = 1792 blocks
    // 4 fused kernels: steps (0,1), (2,3), (4,5), (6,7); each also copies
    // one quarter of ch1-3 into the output.
    for (int k = 0; k < 4; k++) {
        const int s = 2 * k;
        const float* src;  int sstride;
        float*       dst;  int dstride;
        if (k == 0) { src = x;  sstride = NCH * PLANE; }
        else        { src = (k & 1) ? bufA : bufB; sstride = PLANE; }
        if (k == 3) { dst = out; dstride = NCH * PLANE; }
        else        { dst = (k & 1) ? bufB : bufA; dstride = PLANE; }
        fused2_kernel<<<fgrid, 256>>>(src, sstride, dst, dstride,
                                      x, out, Wm, bb, t, s);
    }
}

// round 13
// speedup vs baseline: 1.0016x; 1.0016x over previous
#include <cuda_runtime.h>

#define BATCH 32
#define NCH   4
#define HH    512
#define WW    512
#define PLANE (HH*WW)          /* 262144 */
#define NSTEPS 8
#define D_SCALE 0.2f
#define RHO_SCALE 0.1f
#define FULLM 0xffffffffu

/* ch1-3 of one batch = 3*PLANE floats = 196608 float4; quarter = 49152 f4.
   32 stencil blocks/batch x 256 thr x 6 f4 = 49152.  */

// Ping-pong scratch for the evolving channel-0 field (2 x 32 MiB).
__device__ float g_buf0[BATCH * PLANE];
__device__ float g_buf1[BATCH * PLANE];
// Sums at even steps 0,2,4,6,8: slot k = state entering fused kernel k.
__device__ float g_sum0[5 * BATCH];
__device__ float g_sumsq[5 * BATCH];
// Constant sums of channels 1..3 (index (c-1)*BATCH + b).
__device__ float g_sumc[3 * BATCH];

__global__ void zero_sums_kernel() {
    int i = threadIdx.x;
    if (i < 5 * BATCH) { g_sum0[i] = 0.0f; g_sumsq[i] = 0.0f; }
    if (i < 3 * BATCH) g_sumc[i] = 0.0f;
}

// Reduce all per-(batch,channel) sums (+ sumsq for ch0). Read-only.
// grid = (PLANE/4/256, BATCH*NCH), block = 256.
__global__ void sums_kernel(const float* __restrict__ x) {
    const int p = blockIdx.y;            // plane id = b*4 + c
    const int b = p >> 2;
    const int c = p & 3;
    const int i = blockIdx.x * blockDim.x + threadIdx.x;

    const float4 v = ((const float4*)(x + (size_t)p * PLANE))[i];
    float s  = (v.x + v.y) + (v.z + v.w);
    float s2 = (v.x * v.x + v.y * v.y) + (v.z * v.z + v.w * v.w);

    #pragma unroll
    for (int o = 16; o > 0; o >>= 1) {
        s  += __shfl_down_sync(FULLM, s,  o);
        s2 += __shfl_down_sync(FULLM, s2, o);
    }
    __shared__ float ws[8], ws2[8];
    const int lane = threadIdx.x & 31;
    const int w    = threadIdx.x >> 5;
    if (lane == 0) { ws[w] = s; ws2[w] = s2; }
    __syncthreads();
    if (w == 0) {
        s  = (lane < 8) ? ws[lane]  : 0.0f;
        s2 = (lane < 8) ? ws2[lane] : 0.0f;
        #pragma unroll
        for (int o = 4; o > 0; o >>= 1) {
            s  += __shfl_down_sync(0x000000ffu, s,  o);
            s2 += __shfl_down_sync(0x000000ffu, s2, o);
        }
        if (lane == 0) {
            if (c == 0) {
                atomicAdd(&g_sum0[b],  s);
                atomicAdd(&g_sumsq[b], s2);
            } else {
                atomicAdd(&g_sumc[(c - 1) * BATCH + b], s);
            }
        }
    }
}

// TWO fused reaction-diffusion steps, warp-private, + embedded copy epilogue:
// each block also copies 1536 float4 of ch1-3 (quarter `slot` per kernel),
// preserving R10's wave structure (same 1024 blocks, regs<=64).
//   sum_{s+1} = sum_s + rho_s*(sum_s - sumsq_s)   (periodic: sum(lap)=0)
// grid = (HH/16, BATCH) = (32, 32), block = 256 (8 warps: 4 chunks x 2 grps).
__global__ __launch_bounds__(256, 4) void fused2_kernel(
        const float* __restrict__ src, int src_bstride,
        float* __restrict__ dst, int dst_bstride,
        const float* __restrict__ xin, float* __restrict__ outp,
        const float* __restrict__ Wm,
        const float* __restrict__ bias,
        const int* __restrict__ t, int s) {
    const int b    = blockIdx.y;
    const int tid  = threadIdx.x;
    const int lane = tid & 31;
    const int wid  = tid >> 5;
    const int chunk = wid & 3;
    const int grp   = wid >> 2;                 // 0 or 1
    const int y0    = blockIdx.x * 16 + grp * 8;
    const int slot  = s >> 1;

    const float* __restrict__ u = src + (size_t)b * src_bstride;
    float* __restrict__ v       = dst + (size_t)b * dst_bstride;

    const int xb  = chunk << 7;
    const int x4  = xb + (lane << 2);
    const int xl2 = (xb + WW - 2) & (WW - 1);   // cols xb-2, xb-1 (float2)
    const int xr2 = (xb + 128) & (WW - 1);      // cols xb+128, xb+129 (float2)

    // ---- Edge data for 12 rows (lanes 0..11), issued first ----
    float2 eL = make_float2(0.f, 0.f), eR = make_float2(0.f, 0.f);
    float sxb = 0.0f, sxbr = 0.0f;
    if (lane < 12) {
        const int row = ((y0 - 2 + lane) & (HH - 1)) << 9;
        eL   = *(const float2*)(u + row + xl2);   // (xb-2, xb-1)
        eR   = *(const float2*)(u + row + xr2);   // (xb+128, xb+129)
        sxb  = u[row + xb];                       // col xb
        sxbr = u[row + xb + 127];                 // col xb+127
    }

    // ---- Software-pipelined main-row loads: preload 5 of 12 ----
    float4 R[12];
    #pragma unroll
    for (int k = 0; k < 5; k++)
        R[k] = *(const float4*)(u + (((y0 - 2 + k) & (HH - 1)) << 9) + x4);

    // ---- D/rho for both sub-steps (overlaps loads) ----
    const float inv = 1.0f / (float)PLANE;
    const float sum_s = g_sum0[slot * BATCH + b];
    const float ssq_s = g_sumsq[slot * BATCH + b];
    const float f1 = g_sumc[0 * BATCH + b] * inv;
    const float f2 = g_sumc[1 * BATCH + b] * inv;
    const float f3 = g_sumc[2 * BATCH + b] * inv;
    const float zc0 = f1 * Wm[2] + f2 * Wm[4] + f3 * Wm[6] + bias[0];
    const float zc1 = f1 * Wm[3] + f2 * Wm[5] + f3 * Wm[7] + bias[1];
    const int tb = t[b];

    const float f0 = sum_s * inv;
    float D0 = D_SCALE   / (1.0f + __expf(-(f0 * Wm[0] + zc0)));
    float r0 = RHO_SCALE / (1.0f + __expf(-(f0 * Wm[1] + zc1)));
    if (tb <= s) { D0 = 0.0f; r0 = 0.0f; }

    const float sum_n = sum_s + r0 * (sum_s - ssq_s);   // exact (periodic BC)
    const float f0n = sum_n * inv;
    float D1 = D_SCALE   / (1.0f + __expf(-(f0n * Wm[0] + zc0)));
    float r1 = RHO_SCALE / (1.0f + __expf(-(f0n * Wm[1] + zc1)));
    if (tb <= s + 1) { D1 = 0.0f; r1 = 0.0f; }

    // ---- Edge intermediates: lane i = row y0-2+i (valid i=1..10) ----
    float iLv, iRv;
    {
        float up = __shfl_up_sync(FULLM, eL.y, 1);
        float dn = __shfl_down_sync(FULLM, eL.y, 1);
        iLv = fmaf(D0, up + dn + eL.x + sxb - 4.0f * eL.y,
                   fmaf(r0 * eL.y, 1.0f - eL.y, eL.y));
        up = __shfl_up_sync(FULLM, eR.x, 1);
        dn = __shfl_down_sync(FULLM, eR.x, 1);
        iRv = fmaf(D0, up + dn + sxbr + eR.y - 4.0f * eR.x,
                   fmaf(r0 * eR.x, 1.0f - eR.x, eR.x));
    }

    // ---- Main loop: intermediates m=0..9 (rows y0-1..y0+8), outputs j=m-2 ----
    float4 I[3];
    float acc = 0.0f, acc2 = 0.0f;
    #pragma unroll
    for (int m = 0; m < 10; m++) {
        if (m + 5 < 12)
            R[m + 5] = *(const float4*)(u + (((y0 + 3 + m) & (HH - 1)) << 9) + x4);

        const float4 P = R[m], C = R[m + 1], N = R[m + 2];
        const float lein = __shfl_sync(FULLM, eL.y, m + 1);
        const float riin = __shfl_sync(FULLM, eR.x, m + 1);
        float le = __shfl_up_sync(FULLM, C.w, 1);
        float ri = __shfl_down_sync(FULLM, C.x, 1);
        if (lane == 0)  le = lein;
        if (lane == 31) ri = riin;

        float4 o;
        o.x = fmaf(D0, P.x + N.x + le  + C.y - 4.0f * C.x, fmaf(r0 * C.x, 1.0f - C.x, C.x));
        o.y = fmaf(D0, P.y + N.y + C.x + C.z - 4.0f * C.y, fmaf(r0 * C.y, 1.0f - C.y, C.y));
        o.z = fmaf(D0, P.z + N.z + C.y + C.w - 4.0f * C.z, fmaf(r0 * C.z, 1.0f - C.z, C.z));
        o.w = fmaf(D0, P.w + N.w + C.z + ri  - 4.0f * C.w, fmaf(r0 * C.w, 1.0f - C.w, C.w));
        I[m % 3] = o;

        if (m >= 2) {
            const int j = m - 2;                      // output row y0+j
            const float4 Pm = I[j % 3];
            const float4 Cm = I[(j + 1) % 3];
            const float4 Nm = I[(j + 2) % 3];
            const float leo = __shfl_sync(FULLM, iLv, j + 2);
            const float rio = __shfl_sync(FULLM, iRv, j + 2);
            float le2 = __shfl_up_sync(FULLM, Cm.w, 1);
            float ri2 = __shfl_down_sync(FULLM, Cm.x, 1);
            if (lane == 0)  le2 = leo;
            if (lane == 31) ri2 = rio;

            float4 q;
            q.x = fmaf(D1, Pm.x + Nm.x + le2 + Cm.y - 4.0f * Cm.x, fmaf(r1 * Cm.x, 1.0f - Cm.x, Cm.x));
            q.y = fmaf(D1, Pm.y + Nm.y + Cm.x + Cm.z - 4.0f * Cm.y, fmaf(r1 * Cm.y, 1.0f - Cm.y, Cm.y));
            q.z = fmaf(D1, Pm.z + Nm.z + Cm.y + Cm.w - 4.0f * Cm.z, fmaf(r1 * Cm.z, 1.0f - Cm.z, Cm.z));
            q.w = fmaf(D1, Pm.w + Nm.w + Cm.z + ri2  - 4.0f * Cm.w, fmaf(r1 * Cm.w, 1.0f - Cm.w, Cm.w));

            *(float4*)(v + ((y0 + j) << 9) + x4) = q;
            acc  += (q.x + q.y) + (q.z + q.w);
            acc2 += (q.x * q.x + q.y * q.y) + (q.z * q.z + q.w * q.w);
        }
    }

    // ---- Copy epilogue: 6 float4 of ch1-3 (stencil regs now dead) ----
    {
        const size_t base4 = ((size_t)(b * NCH + 1) * PLANE) >> 2;
        const size_t off   = base4 + (size_t)slot * 49152
                           + (size_t)blockIdx.x * 1536 + tid;
        const float4* __restrict__ sp = (const float4*)xin + off;
        float4* __restrict__ dp       = (float4*)outp + off;
        float4 c0 = sp[0], c1 = sp[256], c2 = sp[512];
        float4 c3 = sp[768], c4 = sp[1024], c5 = sp[1280];
        dp[0] = c0; dp[256] = c1; dp[512] = c2;
        dp[768] = c3; dp[1024] = c4; dp[1280] = c5;
    }

    // ---- Block reduction of sum & sumsq, one atomic pair per block ----
    #pragma unroll
    for (int o = 16; o > 0; o >>= 1) {
        acc  += __shfl_down_sync(FULLM, acc,  o);
        acc2 += __shfl_down_sync(FULLM, acc2, o);
    }
    __shared__ float ws[8], ws2[8];
    if (lane == 0) { ws[wid] = acc; ws2[wid] = acc2; }
    __syncthreads();
    if (wid == 0) {
        acc  = (lane < 8) ? ws[lane]  : 0.0f;
        acc2 = (lane < 8) ? ws2[lane] : 0.0f;
        #pragma unroll
        for (int o = 4; o > 0; o >>= 1) {
            acc  += __shfl_down_sync(0x000000ffu, acc,  o);
            acc2 += __shfl_down_sync(0x000000ffu, acc2, o);
        }
        if (lane == 0) {
            atomicAdd(&g_sum0[(slot + 1) * BATCH + b],  acc);
            atomicAdd(&g_sumsq[(slot + 1) * BATCH + b], acc2);
        }
    }
}

extern "C" void kernel_launch(void* const* d_in, const int* in_sizes, int n_in,
                              void* d_out, int out_size) {
    const float* x  = (const float*)d_in[0];   // (32,4,512,512)
    const float* Wm = (const float*)d_in[1];   // (4,2)
    const float* bb = (const float*)d_in[2];   // (2,)
    const int*   t  = (const int*)d_in[3];     // (32,)
    float* out = (float*)d_out;

    zero_sums_kernel<<<1, 256>>>();

    // All per-(b,c) sums (+ sumsq ch0); read-only pass.
    sums_kernel<<<dim3(PLANE / 4 / 256, BATCH * NCH), dim3(256)>>>(x);

    float* bufA; float* bufB;
    cudaGetSymbolAddress((void**)&bufA, g_buf0);
    cudaGetSymbolAddress((void**)&bufB, g_buf1);

    const dim3 fgrid(HH / 16, BATCH);   // (32, 32) = 1024 blocks (as R10)
    // 4 fused kernels: steps (0,1), (2,3), (4,5), (6,7); each also copies
    // one quarter of ch1-3 into the output via the per-block epilogue.
    for (int k = 0; k < 4; k++) {
        const int s = 2 * k;
        const float* src;  int sstride;
        float*       dst;  int dstride;
        if (k == 0) { src = x;  sstride = NCH * PLANE; }
        else        { src = (k & 1) ? bufA : bufB; sstride = PLANE; }
        if (k == 3) { dst = out; dstride = NCH * PLANE; }
        else        { dst = (k & 1) ? bufB : bufA; dstride = PLANE; }
        fused2_kernel<<<fgrid, 256>>>(src, sstride, dst, dstride,
                                      x, out, Wm, bb, t, s);
    }
}

// round 14
// speedup vs baseline: 1.0027x; 1.0011x over previous
#include <cuda_runtime.h>

#define BATCH 32
#define NCH   4
#define HH    512
#define WW    512
#define PLANE (HH*WW)          /* 262144 */
#define NSTEPS 8
#define D_SCALE 0.2f
#define RHO_SCALE 0.1f
#define FULLM 0xffffffffu

// Ping-pong scratch for the evolving channel-0 field (2 x 32 MiB).
__device__ float g_buf0[BATCH * PLANE];
__device__ float g_buf1[BATCH * PLANE];
// Sums at even steps 0,2,4,6,8: slot k = state entering fused kernel k.
__device__ float g_sum0[5 * BATCH];
__device__ float g_sumsq[5 * BATCH];
// Constant sums of channels 1..3 (index (c-1)*BATCH + b).
__device__ float g_sumc[3 * BATCH];

__global__ void zero_sums_kernel() {
    int i = threadIdx.x;
    if (i < 5 * BATCH) { g_sum0[i] = 0.0f; g_sumsq[i] = 0.0f; }
    if (i < 3 * BATCH) g_sumc[i] = 0.0f;
}

// Reduce all per-(batch,channel) sums (+ sumsq for ch0). Read-only, MLP=8.
// grid = (32, BATCH*NCH), block = 256; thread: 8 strided float4.
__global__ void sums_kernel(const float* __restrict__ x) {
    const int p = blockIdx.y;            // plane id = b*4 + c
    const int b = p >> 2;
    const int c = p & 3;
    const float4* __restrict__ sp =
        (const float4*)(x + (size_t)p * PLANE) + blockIdx.x * 2048 + threadIdx.x;

    float4 v[8];
    #pragma unroll
    for (int j = 0; j < 8; j++) v[j] = sp[j * 256];

    float s = 0.0f, s2 = 0.0f;
    #pragma unroll
    for (int j = 0; j < 8; j++) {
        s  += (v[j].x + v[j].y) + (v[j].z + v[j].w);
        s2 += (v[j].x * v[j].x + v[j].y * v[j].y) + (v[j].z * v[j].z + v[j].w * v[j].w);
    }

    #pragma unroll
    for (int o = 16; o > 0; o >>= 1) {
        s  += __shfl_down_sync(FULLM, s,  o);
        s2 += __shfl_down_sync(FULLM, s2, o);
    }
    __shared__ float ws[8], ws2[8];
    const int lane = threadIdx.x & 31;
    const int w    = threadIdx.x >> 5;
    if (lane == 0) { ws[w] = s; ws2[w] = s2; }
    __syncthreads();
    if (w == 0) {
        s  = (lane < 8) ? ws[lane]  : 0.0f;
        s2 = (lane < 8) ? ws2[lane] : 0.0f;
        #pragma unroll
        for (int o = 4; o > 0; o >>= 1) {
            s  += __shfl_down_sync(0x000000ffu, s,  o);
            s2 += __shfl_down_sync(0x000000ffu, s2, o);
        }
        if (lane == 0) {
            if (c == 0) {
                atomicAdd(&g_sum0[b],  s);
                atomicAdd(&g_sumsq[b], s2);
            } else {
                atomicAdd(&g_sumc[(c - 1) * BATCH + b], s);
            }
        }
    }
}

// Copy ch1..3 for all batches (runs on the PARALLEL stream branch).
// grid = (96, BATCH), block = 256; thread: 8 strided float4.
__global__ void copy_kernel(const float* __restrict__ x, float* __restrict__ out) {
    const size_t off = (((size_t)(blockIdx.y * NCH + 1) * PLANE) >> 2)
                     + (size_t)blockIdx.x * 2048 + threadIdx.x;
    const float4* __restrict__ sp = (const float4*)x + off;
    float4* __restrict__ dp       = (float4*)out + off;
    #pragma unroll
    for (int j = 0; j < 8; j++)
        dp[j * 256] = sp[j * 256];
}

// TWO fused reaction-diffusion steps, warp-private (R10 engine, unchanged).
//   sum_{s+1} = sum_s + rho_s*(sum_s - sumsq_s)   (periodic: sum(lap)=0)
// grid = (HH/16, BATCH) = (32, 32), block = 256 (8 warps: 4 chunks x 2 grps).
__global__ __launch_bounds__(256, 4) void fused2_kernel(
        const float* __restrict__ src, int src_bstride,
        float* __restrict__ dst, int dst_bstride,
        const float* __restrict__ Wm,
        const float* __restrict__ bias,
        const int* __restrict__ t, int s) {
    const int b    = blockIdx.y;
    const int tid  = threadIdx.x;
    const int lane = tid & 31;
    const int wid  = tid >> 5;
    const int chunk = wid & 3;
    const int grp   = wid >> 2;                 // 0 or 1
    const int y0    = blockIdx.x * 16 + grp * 8;
    const int slot  = s >> 1;

    const float* __restrict__ u = src + (size_t)b * src_bstride;
    float* __restrict__ v       = dst + (size_t)b * dst_bstride;

    const int xb  = chunk << 7;
    const int x4  = xb + (lane << 2);
    const int xl2 = (xb + WW - 2) & (WW - 1);   // cols xb-2, xb-1 (float2)
    const int xr2 = (xb + 128) & (WW - 1);      // cols xb+128, xb+129 (float2)

    // ---- Edge data for 12 rows (lanes 0..11), issued first ----
    float2 eL = make_float2(0.f, 0.f), eR = make_float2(0.f, 0.f);
    float sxb = 0.0f, sxbr = 0.0f;
    if (lane < 12) {
        const int row = ((y0 - 2 + lane) & (HH - 1)) << 9;
        eL   = *(const float2*)(u + row + xl2);   // (xb-2, xb-1)
        eR   = *(const float2*)(u + row + xr2);   // (xb+128, xb+129)
        sxb  = u[row + xb];                       // col xb
        sxbr = u[row + xb + 127];                 // col xb+127
    }

    // ---- Software-pipelined main-row loads: preload 5 of 12 ----
    float4 R[12];
    #pragma unroll
    for (int k = 0; k < 5; k++)
        R[k] = *(const float4*)(u + (((y0 - 2 + k) & (HH - 1)) << 9) + x4);

    // ---- D/rho for both sub-steps (overlaps loads) ----
    const float inv = 1.0f / (float)PLANE;
    const float sum_s = g_sum0[slot * BATCH + b];
    const float ssq_s = g_sumsq[slot * BATCH + b];
    const float f1 = g_sumc[0 * BATCH + b] * inv;
    const float f2 = g_sumc[1 * BATCH + b] * inv;
    const float f3 = g_sumc[2 * BATCH + b] * inv;
    const float zc0 = f1 * Wm[2] + f2 * Wm[4] + f3 * Wm[6] + bias[0];
    const float zc1 = f1 * Wm[3] + f2 * Wm[5] + f3 * Wm[7] + bias[1];
    const int tb = t[b];

    const float f0 = sum_s * inv;
    float D0 = D_SCALE   / (1.0f + __expf(-(f0 * Wm[0] + zc0)));
    float r0 = RHO_SCALE / (1.0f + __expf(-(f0 * Wm[1] + zc1)));
    if (tb <= s) { D0 = 0.0f; r0 = 0.0f; }

    const float sum_n = sum_s + r0 * (sum_s - ssq_s);   // exact (periodic BC)
    const float f0n = sum_n * inv;
    float D1 = D_SCALE   / (1.0f + __expf(-(f0n * Wm[0] + zc0)));
    float r1 = RHO_SCALE / (1.0f + __expf(-(f0n * Wm[1] + zc1)));
    if (tb <= s + 1) { D1 = 0.0f; r1 = 0.0f; }

    // ---- Edge intermediates: lane i = row y0-2+i (valid i=1..10) ----
    float iLv, iRv;
    {
        float up = __shfl_up_sync(FULLM, eL.y, 1);
        float dn = __shfl_down_sync(FULLM, eL.y, 1);
        iLv = fmaf(D0, up + dn + eL.x + sxb - 4.0f * eL.y,
                   fmaf(r0 * eL.y, 1.0f - eL.y, eL.y));
        up = __shfl_up_sync(FULLM, eR.x, 1);
        dn = __shfl_down_sync(FULLM, eR.x, 1);
        iRv = fmaf(D0, up + dn + sxbr + eR.y - 4.0f * eR.x,
                   fmaf(r0 * eR.x, 1.0f - eR.x, eR.x));
    }

    // ---- Main loop: intermediates m=0..9 (rows y0-1..y0+8), outputs j=m-2 ----
    float4 I[3];
    float acc = 0.0f, acc2 = 0.0f;
    #pragma unroll
    for (int m = 0; m < 10; m++) {
        if (m + 5 < 12)
            R[m + 5] = *(const float4*)(u + (((y0 + 3 + m) & (HH - 1)) << 9) + x4);

        const float4 P = R[m], C = R[m + 1], N = R[m + 2];
        const float lein = __shfl_sync(FULLM, eL.y, m + 1);
        const float riin = __shfl_sync(FULLM, eR.x, m + 1);
        float le = __shfl_up_sync(FULLM, C.w, 1);
        float ri = __shfl_down_sync(FULLM, C.x, 1);
        if (lane == 0)  le = lein;
        if (lane == 31) ri = riin;

        float4 o;
        o.x = fmaf(D0, P.x + N.x + le  + C.y - 4.0f * C.x, fmaf(r0 * C.x, 1.0f - C.x, C.x));
        o.y = fmaf(D0, P.y + N.y + C.x + C.z - 4.0f * C.y, fmaf(r0 * C.y, 1.0f - C.y, C.y));
        o.z = fmaf(D0, P.z + N.z + C.y + C.w - 4.0f * C.z, fmaf(r0 * C.z, 1.0f - C.z, C.z));
        o.w = fmaf(D0, P.w + N.w + C.z + ri  - 4.0f * C.w, fmaf(r0 * C.w, 1.0f - C.w, C.w));
        I[m % 3] = o;

        if (m >= 2) {
            const int j = m - 2;                      // output row y0+j
            const float4 Pm = I[j % 3];
            const float4 Cm = I[(j + 1) % 3];
            const float4 Nm = I[(j + 2) % 3];
            const float leo = __shfl_sync(FULLM, iLv, j + 2);
            const float rio = __shfl_sync(FULLM, iRv, j + 2);
            float le2 = __shfl_up_sync(FULLM, Cm.w, 1);
            float ri2 = __shfl_down_sync(FULLM, Cm.x, 1);
            if (lane == 0)  le2 = leo;
            if (lane == 31) ri2 = rio;

            float4 q;
            q.x = fmaf(D1, Pm.x + Nm.x + le2 + Cm.y - 4.0f * Cm.x, fmaf(r1 * Cm.x, 1.0f - Cm.x, Cm.x));
            q.y = fmaf(D1, Pm.y + Nm.y + Cm.x + Cm.z - 4.0f * Cm.y, fmaf(r1 * Cm.y, 1.0f - Cm.y, Cm.y));
            q.z = fmaf(D1, Pm.z + Nm.z + Cm.y + Cm.w - 4.0f * Cm.z, fmaf(r1 * Cm.z, 1.0f - Cm.z, Cm.z));
            q.w = fmaf(D1, Pm.w + Nm.w + Cm.z + ri2  - 4.0f * Cm.w, fmaf(r1 * Cm.w, 1.0f - Cm.w, Cm.w));

            *(float4*)(v + ((y0 + j) << 9) + x4) = q;
            acc  += (q.x + q.y) + (q.z + q.w);
            acc2 += (q.x * q.x + q.y * q.y) + (q.z * q.z + q.w * q.w);
        }
    }

    // ---- Block reduction of sum & sumsq, one atomic pair per block ----
    #pragma unroll
    for (int o = 16; o > 0; o >>= 1) {
        acc  += __shfl_down_sync(FULLM, acc,  o);
        acc2 += __shfl_down_sync(FULLM, acc2, o);
    }
    __shared__ float ws[8], ws2[8];
    if (lane == 0) { ws[wid] = acc; ws2[wid] = acc2; }
    __syncthreads();
    if (wid == 0) {
        acc  = (lane < 8) ? ws[lane]  : 0.0f;
        acc2 = (lane < 8) ? ws2[lane] : 0.0f;
        #pragma unroll
        for (int o = 4; o > 0; o >>= 1) {
            acc  += __shfl_down_sync(0x000000ffu, acc,  o);
            acc2 += __shfl_down_sync(0x000000ffu, acc2, o);
        }
        if (lane == 0) {
            atomicAdd(&g_sum0[(slot + 1) * BATCH + b],  acc);
            atomicAdd(&g_sumsq[(slot + 1) * BATCH + b], acc2);
        }
    }
}

extern "C" void kernel_launch(void* const* d_in, const int* in_sizes, int n_in,
                              void* d_out, int out_size) {
    const float* x  = (const float*)d_in[0];   // (32,4,512,512)
    const float* Wm = (const float*)d_in[1];   // (4,2)
    const float* bb = (const float*)d_in[2];   // (2,)
    const int*   t  = (const int*)d_in[3];     // (32,)
    float* out = (float*)d_out;

    // One-time host-side resources (no device memory involved).
    static cudaStream_t s2 = 0;
    static cudaEvent_t evFork = 0, evJoin = 0;
    if (s2 == 0) {
        cudaStreamCreateWithFlags(&s2, cudaStreamNonBlocking);
        cudaEventCreateWithFlags(&evFork, cudaEventDisableTiming);
        cudaEventCreateWithFlags(&evJoin, cudaEventDisableTiming);
    }

    // ---- Fork: ch1-3 copy runs concurrently with the whole chain ----
    cudaEventRecord(evFork, 0);
    cudaStreamWaitEvent(s2, evFork, 0);
    copy_kernel<<<dim3(96, BATCH), 256, 0, s2>>>(x, out);
    cudaEventRecord(evJoin, s2);

    // ---- Main branch: sums -> 4 fused double-steps ----
    zero_sums_kernel<<<1, 256>>>();
    sums_kernel<<<dim3(32, BATCH * NCH), 256>>>(x);

    float* bufA; float* bufB;
    cudaGetSymbolAddress((void**)&bufA, g_buf0);
    cudaGetSymbolAddress((void**)&bufB, g_buf1);

    const dim3 fgrid(HH / 16, BATCH);   // (32, 32) = 1024 blocks
    for (int k = 0; k < 4; k++) {
        const int s = 2 * k;
        const float* src;  int sstride;
        float*       dst;  int dstride;
        if (k == 0) { src = x;  sstride = NCH * PLANE; }
        else        { src = (k & 1) ? bufA : bufB; sstride = PLANE; }
        if (k == 3) { dst = out; dstride = NCH * PLANE; }
        else        { dst = (k & 1) ? bufB : bufA; dstride = PLANE; }
        fused2_kernel<<<fgrid, 256>>>(src, sstride, dst, dstride, Wm, bb, t, s);
    }

    // ---- Join: make graph end depend on the copy branch too ----
    cudaStreamWaitEvent(0, evJoin, 0);
}

// round 15
// speedup vs baseline: 1.1580x; 1.1548x over previous
#include <cuda_runtime.h>

#define BATCH 32
#define NCH   4
#define HH    512
#define WW    512
#define PLANE (HH*WW)          /* 262144 */
#define NSTEPS 8
#define D_SCALE 0.2f
#define RHO_SCALE 0.1f
#define FULLM 0xffffffffu

typedef unsigned long long u64t;

// Ping-pong scratch for the evolving channel-0 field (2 x 32 MiB).
__device__ float g_buf0[BATCH * PLANE];
__device__ float g_buf1[BATCH * PLANE];
// Sums at even steps 0,2,4,6,8: slot k = state entering fused kernel k.
__device__ float g_sum0[5 * BATCH];
__device__ float g_sumsq[5 * BATCH];
// Constant sums of channels 1..3 (index (c-1)*BATCH + b).
__device__ float g_sumc[3 * BATCH];

__global__ void zero_sums_kernel() {
    int i = threadIdx.x;
    if (i < 5 * BATCH) { g_sum0[i] = 0.0f; g_sumsq[i] = 0.0f; }
    if (i < 3 * BATCH) g_sumc[i] = 0.0f;
}

// Copy channels 1..3 input->output; reduce sums (and sumsq for ch0).
// R10 version: one read of x serves both copy and sums. ~HBM floor.
__global__ void init_kernel(const float* __restrict__ x, float* __restrict__ out) {
    const int p = blockIdx.y;            // plane id = b*4 + c
    const int b = p >> 2;
    const int c = p & 3;
    const int i = blockIdx.x * blockDim.x + threadIdx.x;

    const float4* src = (const float4*)(x + (size_t)p * PLANE);
    float4 v = src[i];
    if (c != 0) {
        ((float4*)(out + (size_t)p * PLANE))[i] = v;
    }
    float s  = (v.x + v.y) + (v.z + v.w);
    float s2 = (v.x * v.x + v.y * v.y) + (v.z * v.z + v.w * v.w);

    #pragma unroll
    for (int o = 16; o > 0; o >>= 1) {
        s  += __shfl_down_sync(FULLM, s,  o);
        s2 += __shfl_down_sync(FULLM, s2, o);
    }
    __shared__ float ws[8], ws2[8];
    const int lane = threadIdx.x & 31;
    const int w    = threadIdx.x >> 5;
    if (lane == 0) { ws[w] = s; ws2[w] = s2; }
    __syncthreads();
    if (w == 0) {
        s  = (lane < 8) ? ws[lane]  : 0.0f;
        s2 = (lane < 8) ? ws2[lane] : 0.0f;
        #pragma unroll
        for (int o = 4; o > 0; o >>= 1) {
            s  += __shfl_down_sync(0x000000ffu, s,  o);
            s2 += __shfl_down_sync(0x000000ffu, s2, o);
        }
        if (lane == 0) {
            if (c == 0) {
                atomicAdd(&g_sum0[b],  s);
                atomicAdd(&g_sumsq[b], s2);
            } else {
                atomicAdd(&g_sumc[(c - 1) * BATCH + b], s);
            }
        }
    }
}

// ---------- packed f32x2 helpers (Blackwell) ----------
__device__ __forceinline__ u64t pk2(float a, float b) {
    u64t r; asm("mov.b64 %0,{%1,%2};" : "=l"(r) : "f"(a), "f"(b)); return r;
}
__device__ __forceinline__ void un2(u64t v, float& a, float& b) {
    asm("mov.b64 {%0,%1},%2;" : "=f"(a), "=f"(b) : "l"(v));
}
__device__ __forceinline__ u64t add2(u64t a, u64t b) {
    u64t r; asm("add.rn.f32x2 %0,%1,%2;" : "=l"(r) : "l"(a), "l"(b)); return r;
}
__device__ __forceinline__ u64t mul2(u64t a, u64t b) {
    u64t r; asm("mul.rn.f32x2 %0,%1,%2;" : "=l"(r) : "l"(a), "l"(b)); return r;
}
__device__ __forceinline__ u64t fma2(u64t a, u64t b, u64t c) {
    u64t r; asm("fma.rn.f32x2 %0,%1,%2,%3;" : "=l"(r) : "l"(a), "l"(b), "l"(c)); return r;
}
__device__ __forceinline__ void ldg2(const float* p, u64t& lo, u64t& hi) {
    asm("ld.global.v2.u64 {%0,%1},[%2];" : "=l"(lo), "=l"(hi) : "l"(p));
}
__device__ __forceinline__ void stg2(float* p, u64t lo, u64t hi) {
    asm volatile("st.global.v2.u64 [%0],{%1,%2};" :: "l"(p), "l"(lo), "l"(hi));
}

#define ONE2_C  0x3F8000003F800000ULL
#define NEG12_C 0xBF800000BF800000ULL
#define NEG42_C 0xC0800000C0800000ULL

// One stencil sub-step on one packed pair: o = C + D*lap + rho*C*(1-C)
__device__ __forceinline__ u64t sp2(u64t Pp, u64t Cp, u64t Np, u64t LEp, u64t RIp,
                                    u64t D2, u64t r2) {
    u64t tt = add2(Pp, Np);
    tt = add2(tt, LEp);
    tt = add2(tt, RIp);
    tt = fma2((u64t)NEG42_C, Cp, tt);         // lap = P+N+LE+RI-4C
    u64t omc  = fma2((u64t)NEG12_C, Cp, (u64t)ONE2_C);  // 1-C
    u64t m    = mul2(r2, Cp);                 // rho*C
    u64t base = fma2(m, omc, Cp);             // C + rho*C*(1-C)
    return fma2(D2, tt, base);
}

// One full row update (4 elements = 2 pairs), horizontals via shfl.
__device__ __forceinline__ void rowstep(u64t Plo, u64t Phi, u64t Clo, u64t Chi,
                                        u64t Nlo, u64t Nhi, float leB, float riB,
                                        int lane, u64t D2, u64t r2,
                                        u64t& olo, u64t& ohi) {
    float cx, cy, cz, cw;
    un2(Clo, cx, cy); un2(Chi, cz, cw);
    float le = __shfl_up_sync(FULLM, cw, 1);
    float ri = __shfl_down_sync(FULLM, cx, 1);
    if (lane == 0)  le = leB;
    if (lane == 31) ri = riB;
    const u64t LElo = pk2(le, cx);
    const u64t mid  = pk2(cy, cz);
    const u64t RIhi = pk2(cw, ri);
    olo = sp2(Plo, Clo, Nlo, LElo, mid,  D2, r2);
    ohi = sp2(Phi, Chi, Nhi, mid,  RIhi, D2, r2);
}

// TWO fused reaction-diffusion steps, warp-private, packed f32x2 math.
//   sum_{s+1} = sum_s + rho_s*(sum_s - sumsq_s)   (periodic: sum(lap)=0)
// FAST: strip needs no row wrap (y0 in [8,496]) -> base + immediate offsets.
template<bool REDUCE, bool FAST>
__device__ __forceinline__ void f2body(
        const float* __restrict__ u, float* __restrict__ v,
        int y0, int lane, int wid, int b,
        const float* __restrict__ Wm, const float* __restrict__ bias,
        const int* __restrict__ t, int s) {
    const int chunk = wid & 3;
    const int slot  = s >> 1;
    const int xb  = chunk << 7;
    const int x4  = xb + (lane << 2);
    const int xl2 = (xb + WW - 2) & (WW - 1);
    const int xr2 = (xb + 128) & (WW - 1);

    // ---- Edge data for 12 rows (lanes 0..11), issued first ----
    float2 eL = make_float2(0.f, 0.f), eR = make_float2(0.f, 0.f);
    float sxb = 0.0f, sxbr = 0.0f;
    if (lane < 12) {
        const int row = ((y0 - 2 + lane) & (HH - 1)) << 9;
        eL   = *(const float2*)(u + row + xl2);
        eR   = *(const float2*)(u + row + xr2);
        sxb  = u[row + xb];
        sxbr = u[row + xb + 127];
    }

    // ---- Software-pipelined main-row loads: preload 5 of 12 (packed) ----
    const float* bp = FAST ? (u + (y0 - 2) * WW + x4) : u;
    u64t Rlo[12], Rhi[12];
    #pragma unroll
    for (int k = 0; k < 5; k++) {
        if (FAST) ldg2(bp + k * WW, Rlo[k], Rhi[k]);
        else      ldg2(u + (((y0 - 2 + k) & (HH - 1)) << 9) + x4, Rlo[k], Rhi[k]);
    }

    // ---- D/rho for both sub-steps ----
    const float inv = 1.0f / (float)PLANE;
    const float sum_s = g_sum0[slot * BATCH + b];
    const float ssq_s = g_sumsq[slot * BATCH + b];
    const float f1 = g_sumc[0 * BATCH + b] * inv;
    const float f2 = g_sumc[1 * BATCH + b] * inv;
    const float f3 = g_sumc[2 * BATCH + b] * inv;
    const float zc0 = f1 * Wm[2] + f2 * Wm[4] + f3 * Wm[6] + bias[0];
    const float zc1 = f1 * Wm[3] + f2 * Wm[5] + f3 * Wm[7] + bias[1];
    const int tb = t[b];

    const float f0 = sum_s * inv;
    float D0 = D_SCALE   / (1.0f + __expf(-(f0 * Wm[0] + zc0)));
    float r0 = RHO_SCALE / (1.0f + __expf(-(f0 * Wm[1] + zc1)));
    if (tb <= s) { D0 = 0.0f; r0 = 0.0f; }

    const float sum_n = sum_s + r0 * (sum_s - ssq_s);   // exact (periodic BC)
    const float f0n = sum_n * inv;
    float D1 = D_SCALE   / (1.0f + __expf(-(f0n * Wm[0] + zc0)));
    float r1 = RHO_SCALE / (1.0f + __expf(-(f0n * Wm[1] + zc1)));
    if (tb <= s + 1) { D1 = 0.0f; r1 = 0.0f; }

    const u64t D0_2 = pk2(D0, D0), R0_2 = pk2(r0, r0);
    const u64t D1_2 = pk2(D1, D1), R1_2 = pk2(r1, r1);

    // ---- Edge intermediates: lane i = row y0-2+i (valid i=1..10) ----
    float iLv, iRv;
    {
        float up = __shfl_up_sync(FULLM, eL.y, 1);
        float dn = __shfl_down_sync(FULLM, eL.y, 1);
        iLv = fmaf(D0, up + dn + eL.x + sxb - 4.0f * eL.y,
                   fmaf(r0 * eL.y, 1.0f - eL.y, eL.y));
        up = __shfl_up_sync(FULLM, eR.x, 1);
        dn = __shfl_down_sync(FULLM, eR.x, 1);
        iRv = fmaf(D0, up + dn + sxbr + eR.y - 4.0f * eR.x,
                   fmaf(r0 * eR.x, 1.0f - eR.x, eR.x));
    }

    float* vb = v + y0 * WW + x4;

    // ---- Main loop: intermediates m=0..9 (rows y0-1..y0+8), outputs j=m-2 ----
    u64t Ilo[3], Ihi[3];
    u64t accS = 0, accQ = 0;   // packed (0.0f,0.0f)
    #pragma unroll
    for (int m = 0; m < 10; m++) {
        if (m + 5 < 12) {
            if (FAST) ldg2(bp + (m + 5) * WW, Rlo[m + 5], Rhi[m + 5]);
            else      ldg2(u + (((y0 + 3 + m) & (HH - 1)) << 9) + x4,
                           Rlo[m + 5], Rhi[m + 5]);
        }

        const float leB = __shfl_sync(FULLM, eL.y, m + 1);
        const float riB = __shfl_sync(FULLM, eR.x, m + 1);
        rowstep(Rlo[m], Rhi[m], Rlo[m + 1], Rhi[m + 1], Rlo[m + 2], Rhi[m + 2],
                leB, riB, lane, D0_2, R0_2, Ilo[m % 3], Ihi[m % 3]);

        if (m >= 2) {
            const int j = m - 2;
            const float leo = __shfl_sync(FULLM, iLv, j + 2);
            const float rio = __shfl_sync(FULLM, iRv, j + 2);
            u64t qlo, qhi;
            rowstep(Ilo[j % 3], Ihi[j % 3], Ilo[(j + 1) % 3], Ihi[(j + 1) % 3],
                    Ilo[(j + 2) % 3], Ihi[(j + 2) % 3],
                    leo, rio, lane, D1_2, R1_2, qlo, qhi);
            stg2(vb + j * WW, qlo, qhi);
            if (REDUCE) {
                accS = add2(accS, qlo);
                accS = add2(accS, qhi);
                accQ = fma2(qlo, qlo, accQ);
                accQ = fma2(qhi, qhi, accQ);
            }
        }
    }

    if (REDUCE) {
        float a0, a1, q0, q1;
        un2(accS, a0, a1); un2(accQ, q0, q1);
        float acc = a0 + a1, acc2 = q0 + q1;
        #pragma unroll
        for (int o = 16; o > 0; o >>= 1) {
            acc  += __shfl_down_sync(FULLM, acc,  o);
            acc2 += __shfl_down_sync(FULLM, acc2, o);
        }
        __shared__ float ws[8], ws2[8];
        if (lane == 0) { ws[wid] = acc; ws2[wid] = acc2; }
        __syncthreads();
        if (wid == 0) {
            acc  = (lane < 8) ? ws[lane]  : 0.0f;
            acc2 = (lane < 8) ? ws2[lane] : 0.0f;
            #pragma unroll
            for (int o = 4; o > 0; o >>= 1) {
                acc  += __shfl_down_sync(0x000000ffu, acc,  o);
                acc2 += __shfl_down_sync(0x000000ffu, acc2, o);
            }
            if (lane == 0) {
                atomicAdd(&g_sum0[(slot + 1) * BATCH + b],  acc);
                atomicAdd(&g_sumsq[(slot + 1) * BATCH + b], acc2);
            }
        }
    }
}

template<bool REDUCE>
__global__ __launch_bounds__(256, 4) void fused2_kernel(
        const float* __restrict__ src, int src_bstride,
        float* __restrict__ dst, int dst_bstride,
        const float* __restrict__ Wm,
        const float* __restrict__ bias,
        const int* __restrict__ t, int s) {
    const int b    = blockIdx.y;
    const int tid  = threadIdx.x;
    const int lane = tid & 31;
    const int wid  = tid >> 5;
    const int grp  = wid >> 2;
    const int y0   = blockIdx.x * 16 + grp * 8;

    const float* __restrict__ u = src + (size_t)b * src_bstride;
    float* __restrict__ v       = dst + (size_t)b * dst_bstride;

    if (y0 >= 8 && y0 <= 496)
        f2body<REDUCE, true >(u, v, y0, lane, wid, b, Wm, bias, t, s);
    else
        f2body<REDUCE, false>(u, v, y0, lane, wid, b, Wm, bias, t, s);
}

extern "C" void kernel_launch(void* const* d_in, const int* in_sizes, int n_in,
                              void* d_out, int out_size) {
    const float* x  = (const float*)d_in[0];   // (32,4,512,512)
    const float* Wm = (const float*)d_in[1];   // (4,2)
    const float* bb = (const float*)d_in[2];   // (2,)
    const int*   t  = (const int*)d_in[3];     // (32,)
    float* out = (float*)d_out;

    zero_sums_kernel<<<1, 256>>>();

    // Copy ch1..3, reduce per-(b,c) sums (+ sumsq for ch0).
    init_kernel<<<dim3(PLANE / 4 / 256, BATCH * NCH), dim3(256)>>>(x, out);

    float* bufA; float* bufB;
    cudaGetSymbolAddress((void**)&bufA, g_buf0);
    cudaGetSymbolAddress((void**)&bufB, g_buf1);

    const dim3 fgrid(HH / 16, BATCH);   // (32, 32) = 1024 blocks
    for (int k = 0; k < 4; k++) {
        const int s = 2 * k;
        const float* src;  int sstride;
        float*       dst;  int dstride;
        if (k == 0) { src = x;  sstride = NCH * PLANE; }
        else        { src = (k & 1) ? bufA : bufB; sstride = PLANE; }
        if (k == 3) { dst = out; dstride = NCH * PLANE; }
        else        { dst = (k & 1) ? bufB : bufA; dstride = PLANE; }
        if (k < 3)
            fused2_kernel<true ><<<fgrid, 256>>>(src, sstride, dst, dstride,
                                                 Wm, bb, t, s);
        else
            fused2_kernel<false><<<fgrid, 256>>>(src, sstride, dst, dstride,
                                                 Wm, bb, t, s);
    }
}

// round 16
// speedup vs baseline: 1.1904x; 1.0280x over previous
#include <cuda_runtime.h>

#define BATCH 32
#define NCH   4
#define HH    512
#define WW    512
#define PLANE (HH*WW)          /* 262144 */
#define NSTEPS 8
#define D_SCALE 0.2f
#define RHO_SCALE 0.1f
#define FULLM 0xffffffffu

// Ping-pong scratch for the evolving channel-0 field (2 x 32 MiB).
__device__ float g_buf0[BATCH * PLANE];
__device__ float g_buf1[BATCH * PLANE];
// Sums at even steps 0,2,4,6,8: slot k = state entering fused kernel k.
__device__ float g_sum0[5 * BATCH];
__device__ float g_sumsq[5 * BATCH];
// Constant sums of channels 1..3 (index (c-1)*BATCH + b).
__device__ float g_sumc[3 * BATCH];

__global__ void zero_sums_kernel() {
    int i = threadIdx.x;
    if (i < 5 * BATCH) { g_sum0[i] = 0.0f; g_sumsq[i] = 0.0f; }
    if (i < 3 * BATCH) g_sumc[i] = 0.0f;
}

// Copy channels 1..3 input->output; reduce sums (and sumsq for ch0).
// ch1-3 use streaming loads/stores (read/written once, never again) so L2
// keeps x's ch0 + the ping-pong buffers for the fused chain.
__global__ void init_kernel(const float* __restrict__ x, float* __restrict__ out) {
    const int p = blockIdx.y;            // plane id = b*4 + c
    const int b = p >> 2;
    const int c = p & 3;
    const int i = blockIdx.x * blockDim.x + threadIdx.x;

    const float4* src = (const float4*)(x + (size_t)p * PLANE);
    float4 v;
    if (c != 0) {
        v = __ldcs(src + i);                                  // evict-first
        __stcs(((float4*)(out + (size_t)p * PLANE)) + i, v);  // evict-first
    } else {
        v = __ldg(src + i);                                   // keep cached
    }
    float s  = (v.x + v.y) + (v.z + v.w);
    float s2 = (v.x * v.x + v.y * v.y) + (v.z * v.z + v.w * v.w);

    #pragma unroll
    for (int o = 16; o > 0; o >>= 1) {
        s  += __shfl_down_sync(FULLM, s,  o);
        s2 += __shfl_down_sync(FULLM, s2, o);
    }
    __shared__ float ws[8], ws2[8];
    const int lane = threadIdx.x & 31;
    const int w    = threadIdx.x >> 5;
    if (lane == 0) { ws[w] = s; ws2[w] = s2; }
    __syncthreads();
    if (w == 0) {
        s  = (lane < 8) ? ws[lane]  : 0.0f;
        s2 = (lane < 8) ? ws2[lane] : 0.0f;
        #pragma unroll
        for (int o = 4; o > 0; o >>= 1) {
            s  += __shfl_down_sync(0x000000ffu, s,  o);
            s2 += __shfl_down_sync(0x000000ffu, s2, o);
        }
        if (lane == 0) {
            if (c == 0) {
                atomicAdd(&g_sum0[b],  s);
                atomicAdd(&g_sumsq[b], s2);
            } else {
                atomicAdd(&g_sumc[(c - 1) * BATCH + b], s);
            }
        }
    }
}

// TWO fused reaction-diffusion steps, warp-private (R10 scalar engine).
//   sum_{s+1} = sum_s + rho_s*(sum_s - sumsq_s)   (periodic: sum(lap)=0)
// LAST=true (final kernel): skip the sum reduction (slot 4 never read) and
// use streaming stores (out ch0 is never re-read on-device).
// grid = (HH/16, BATCH) = (32, 32), block = 256 (8 warps: 4 chunks x 2 grps).
template<bool LAST>
__global__ __launch_bounds__(256, 4) void fused2_kernel(
        const float* __restrict__ src, int src_bstride,
        float* __restrict__ dst, int dst_bstride,
        const float* __restrict__ Wm,
        const float* __restrict__ bias,
        const int* __restrict__ t, int s) {
    const int b    = blockIdx.y;
    const int tid  = threadIdx.x;
    const int lane = tid & 31;
    const int wid  = tid >> 5;
    const int chunk = wid & 3;
    const int grp   = wid >> 2;                 // 0 or 1
    const int y0    = blockIdx.x * 16 + grp * 8;
    const int slot  = s >> 1;

    const float* __restrict__ u = src + (size_t)b * src_bstride;
    float* __restrict__ v       = dst + (size_t)b * dst_bstride;

    const int xb  = chunk << 7;
    const int x4  = xb + (lane << 2);
    const int xl2 = (xb + WW - 2) & (WW - 1);   // cols xb-2, xb-1 (float2)
    const int xr2 = (xb + 128) & (WW - 1);      // cols xb+128, xb+129 (float2)

    // ---- Edge data for 12 rows (lanes 0..11), issued first ----
    float2 eL = make_float2(0.f, 0.f), eR = make_float2(0.f, 0.f);
    float sxb = 0.0f, sxbr = 0.0f;
    if (lane < 12) {
        const int row = ((y0 - 2 + lane) & (HH - 1)) << 9;
        eL   = *(const float2*)(u + row + xl2);   // (xb-2, xb-1)
        eR   = *(const float2*)(u + row + xr2);   // (xb+128, xb+129)
        sxb  = u[row + xb];                       // col xb
        sxbr = u[row + xb + 127];                 // col xb+127
    }

    // ---- Software-pipelined main-row loads: preload 5 of 12 ----
    float4 R[12];
    #pragma unroll
    for (int k = 0; k < 5; k++)
        R[k] = *(const float4*)(u + (((y0 - 2 + k) & (HH - 1)) << 9) + x4);

    // ---- D/rho for both sub-steps (overlaps loads) ----
    const float inv = 1.0f / (float)PLANE;
    const float sum_s = g_sum0[slot * BATCH + b];
    const float ssq_s = g_sumsq[slot * BATCH + b];
    const float f1 = g_sumc[0 * BATCH + b] * inv;
    const float f2 = g_sumc[1 * BATCH + b] * inv;
    const float f3 = g_sumc[2 * BATCH + b] * inv;
    const float zc0 = f1 * Wm[2] + f2 * Wm[4] + f3 * Wm[6] + bias[0];
    const float zc1 = f1 * Wm[3] + f2 * Wm[5] + f3 * Wm[7] + bias[1];
    const int tb = t[b];

    const float f0 = sum_s * inv;
    float D0 = D_SCALE   / (1.0f + __expf(-(f0 * Wm[0] + zc0)));
    float r0 = RHO_SCALE / (1.0f + __expf(-(f0 * Wm[1] + zc1)));
    if (tb <= s) { D0 = 0.0f; r0 = 0.0f; }

    const float sum_n = sum_s + r0 * (sum_s - ssq_s);   // exact (periodic BC)
    const float f0n = sum_n * inv;
    float D1 = D_SCALE   / (1.0f + __expf(-(f0n * Wm[0] + zc0)));
    float r1 = RHO_SCALE / (1.0f + __expf(-(f0n * Wm[1] + zc1)));
    if (tb <= s + 1) { D1 = 0.0f; r1 = 0.0f; }

    // ---- Edge intermediates: lane i = row y0-2+i (valid i=1..10) ----
    float iLv, iRv;
    {
        float up = __shfl_up_sync(FULLM, eL.y, 1);
        float dn = __shfl_down_sync(FULLM, eL.y, 1);
        iLv = fmaf(D0, up + dn + eL.x + sxb - 4.0f * eL.y,
                   fmaf(r0 * eL.y, 1.0f - eL.y, eL.y));
        up = __shfl_up_sync(FULLM, eR.x, 1);
        dn = __shfl_down_sync(FULLM, eR.x, 1);
        iRv = fmaf(D0, up + dn + sxbr + eR.y - 4.0f * eR.x,
                   fmaf(r0 * eR.x, 1.0f - eR.x, eR.x));
    }

    // ---- Main loop: intermediates m=0..9 (rows y0-1..y0+8), outputs j=m-2 ----
    float4 I[3];
    float acc = 0.0f, acc2 = 0.0f;
    #pragma unroll
    for (int m = 0; m < 10; m++) {
        if (m + 5 < 12)
            R[m + 5] = *(const float4*)(u + (((y0 + 3 + m) & (HH - 1)) << 9) + x4);

        const float4 P = R[m], C = R[m + 1], N = R[m + 2];
        const float lein = __shfl_sync(FULLM, eL.y, m + 1);
        const float riin = __shfl_sync(FULLM, eR.x, m + 1);
        float le = __shfl_up_sync(FULLM, C.w, 1);
        float ri = __shfl_down_sync(FULLM, C.x, 1);
        if (lane == 0)  le = lein;
        if (lane == 31) ri = riin;

        float4 o;
        o.x = fmaf(D0, P.x + N.x + le  + C.y - 4.0f * C.x, fmaf(r0 * C.x, 1.0f - C.x, C.x));
        o.y = fmaf(D0, P.y + N.y + C.x + C.z - 4.0f * C.y, fmaf(r0 * C.y, 1.0f - C.y, C.y));
        o.z = fmaf(D0, P.z + N.z + C.y + C.w - 4.0f * C.z, fmaf(r0 * C.z, 1.0f - C.z, C.z));
        o.w = fmaf(D0, P.w + N.w + C.z + ri  - 4.0f * C.w, fmaf(r0 * C.w, 1.0f - C.w, C.w));
        I[m % 3] = o;

        if (m >= 2) {
            const int j = m - 2;                      // output row y0+j
            const float4 Pm = I[j % 3];
            const float4 Cm = I[(j + 1) % 3];
            const float4 Nm = I[(j + 2) % 3];
            const float leo = __shfl_sync(FULLM, iLv, j + 2);
            const float rio = __shfl_sync(FULLM, iRv, j + 2);
            float le2 = __shfl_up_sync(FULLM, Cm.w, 1);
            float ri2 = __shfl_down_sync(FULLM, Cm.x, 1);
            if (lane == 0)  le2 = leo;
            if (lane == 31) ri2 = rio;

            float4 q;
            q.x = fmaf(D1, Pm.x + Nm.x + le2 + Cm.y - 4.0f * Cm.x, fmaf(r1 * Cm.x, 1.0f - Cm.x, Cm.x));
            q.y = fmaf(D1, Pm.y + Nm.y + Cm.x + Cm.z - 4.0f * Cm.y, fmaf(r1 * Cm.y, 1.0f - Cm.y, Cm.y));
            q.z = fmaf(D1, Pm.z + Nm.z + Cm.y + Cm.w - 4.0f * Cm.z, fmaf(r1 * Cm.z, 1.0f - Cm.z, Cm.z));
            q.w = fmaf(D1, Pm.w + Nm.w + Cm.z + ri2  - 4.0f * Cm.w, fmaf(r1 * Cm.w, 1.0f - Cm.w, Cm.w));

            float4* dstp = (float4*)(v + ((y0 + j) << 9) + x4);
            if (LAST) __stcs(dstp, q);    // out ch0: never re-read on-device
            else      *dstp = q;          // intermediate: next kernel reads it
            if (!LAST) {
                acc  += (q.x + q.y) + (q.z + q.w);
                acc2 += (q.x * q.x + q.y * q.y) + (q.z * q.z + q.w * q.w);
            }
        }
    }

    if (!LAST) {
        // ---- Block reduction of sum & sumsq, one atomic pair per block ----
        #pragma unroll
        for (int o = 16; o > 0; o >>= 1) {
            acc  += __shfl_down_sync(FULLM, acc,  o);
            acc2 += __shfl_down_sync(FULLM, acc2, o);
        }
        __shared__ float ws[8], ws2[8];
        if (lane == 0) { ws[wid] = acc; ws2[wid] = acc2; }
        __syncthreads();
        if (wid == 0) {
            acc  = (lane < 8) ? ws[lane]  : 0.0f;
            acc2 = (lane < 8) ? ws2[lane] : 0.0f;
            #pragma unroll
            for (int o = 4; o > 0; o >>= 1) {
                acc  += __shfl_down_sync(0x000000ffu, acc,  o);
                acc2 += __shfl_down_sync(0x000000ffu, acc2, o);
            }
            if (lane == 0) {
                atomicAdd(&g_sum0[(slot + 1) * BATCH + b],  acc);
                atomicAdd(&g_sumsq[(slot + 1) * BATCH + b], acc2);
            }
        }
    }
}

extern "C" void kernel_launch(void* const* d_in, const int* in_sizes, int n_in,
                              void* d_out, int out_size) {
    const float* x  = (const float*)d_in[0];   // (32,4,512,512)
    const float* Wm = (const float*)d_in[1];   // (4,2)
    const float* bb = (const float*)d_in[2];   // (2,)
    const int*   t  = (const int*)d_in[3];     // (32,)
    float* out = (float*)d_out;

    zero_sums_kernel<<<1, 256>>>();

    // Copy ch1..3 (streaming), reduce per-(b,c) sums (+ sumsq for ch0).
    init_kernel<<<dim3(PLANE / 4 / 256, BATCH * NCH), dim3(256)>>>(x, out);

    float* bufA; float* bufB;
    cudaGetSymbolAddress((void**)&bufA, g_buf0);
    cudaGetSymbolAddress((void**)&bufB, g_buf1);

    const dim3 fgrid(HH / 16, BATCH);   // (32, 32) = 1024 blocks
    for (int k = 0; k < 4; k++) {
        const int s = 2 * k;
        const float* src;  int sstride;
        float*       dst;  int dstride;
        if (k == 0) { src = x;  sstride = NCH * PLANE; }
        else        { src = (k & 1) ? bufA : bufB; sstride = PLANE; }
        if (k == 3) { dst = out; dstride = NCH * PLANE; }
        else        { dst = (k & 1) ? bufB : bufA; dstride = PLANE; }
        if (k < 3)
            fused2_kernel<false><<<fgrid, 256>>>(src, sstride, dst, dstride,
                                                 Wm, bb, t, s);
        else
            fused2_kernel<true ><<<fgrid, 256>>>(src, sstride, dst, dstride,
                                                 Wm, bb, t, s);
    }
}

// round 17
// speedup vs baseline: 1.2741x; 1.0704x over previous
#include <cuda_runtime.h>

#define BATCH 32
#define NCH   4
#define HH    512
#define WW    512
#define PLANE (HH*WW)          /* 262144 */
#define NSTEPS 8
#define D_SCALE 0.2f
#define RHO_SCALE 0.1f
#define FULLM 0xffffffffu

// Ping-pong scratch for the evolving channel-0 field (2 x 32 MiB).
__device__ float g_buf0[BATCH * PLANE];
__device__ float g_buf1[BATCH * PLANE];
// Sums at even steps 0,2,4,6,8: slot k = state entering fused kernel k.
__device__ float g_sum0[5 * BATCH];
__device__ float g_sumsq[5 * BATCH];
// Constant sums of channels 1..3 (index (c-1)*BATCH + b).
__device__ float g_sumc[3 * BATCH];

__global__ void zero_sums_kernel() {
    int i = threadIdx.x;
    if (i < 5 * BATCH) { g_sum0[i] = 0.0f; g_sumsq[i] = 0.0f; }
    if (i < 3 * BATCH) g_sumc[i] = 0.0f;
}

// Copy channels 1..3 input->output; reduce sums (and sumsq for ch0).
// MLP=4: each thread handles 4 strided float4. ch1-3 use streaming
// loads/stores (touched once) so L2 keeps ch0 + ping-pong buffers.
// grid = (64, BATCH*NCH), block = 256.
__global__ void init_kernel(const float* __restrict__ x, float* __restrict__ out) {
    const int p = blockIdx.y;            // plane id = b*4 + c
    const int b = p >> 2;
    const int c = p & 3;
    const int i0 = blockIdx.x * 1024 + threadIdx.x;

    const float4* src = (const float4*)(x + (size_t)p * PLANE);
    float4* dst       = (float4*)(out + (size_t)p * PLANE);

    float4 v[4];
    if (c != 0) {
        #pragma unroll
        for (int j = 0; j < 4; j++) v[j] = __ldcs(src + i0 + j * 256);
        #pragma unroll
        for (int j = 0; j < 4; j++) __stcs(dst + i0 + j * 256, v[j]);
    } else {
        #pragma unroll
        for (int j = 0; j < 4; j++) v[j] = __ldg(src + i0 + j * 256);
    }

    float s = 0.0f, s2 = 0.0f;
    #pragma unroll
    for (int j = 0; j < 4; j++) {
        s  += (v[j].x + v[j].y) + (v[j].z + v[j].w);
        s2 += (v[j].x * v[j].x + v[j].y * v[j].y) + (v[j].z * v[j].z + v[j].w * v[j].w);
    }

    #pragma unroll
    for (int o = 16; o > 0; o >>= 1) {
        s  += __shfl_down_sync(FULLM, s,  o);
        s2 += __shfl_down_sync(FULLM, s2, o);
    }
    __shared__ float ws[8], ws2[8];
    const int lane = threadIdx.x & 31;
    const int w    = threadIdx.x >> 5;
    if (lane == 0) { ws[w] = s; ws2[w] = s2; }
    __syncthreads();
    if (w == 0) {
        s  = (lane < 8) ? ws[lane]  : 0.0f;
        s2 = (lane < 8) ? ws2[lane] : 0.0f;
        #pragma unroll
        for (int o = 4; o > 0; o >>= 1) {
            s  += __shfl_down_sync(0x000000ffu, s,  o);
            s2 += __shfl_down_sync(0x000000ffu, s2, o);
        }
        if (lane == 0) {
            if (c == 0) {
                atomicAdd(&g_sum0[b],  s);
                atomicAdd(&g_sumsq[b], s2);
            } else {
                atomicAdd(&g_sumc[(c - 1) * BATCH + b], s);
            }
        }
    }
}

// TWO fused reaction-diffusion steps, warp-private, 16-row strips.
//   sum_{s+1} = sum_s + rho_s*(sum_s - sumsq_s)   (periodic: sum(lap)=0)
// Warp = (chunk of 128 cols, strip of 16 output rows): 20 input rows
// software-pipelined (preload 5), 18 intermediates rolled in 3 regs,
// per-warp overhead (edges, sigmoid, reduction) amortized over 2x rows.
// LAST=true: skip reduction, streaming stores.
// grid = (HH/32, BATCH) = (16, 32), block = 256 (8 warps: 4 chunks x 2 grps).
template<bool LAST>
__global__ __launch_bounds__(256, 4) void fused2_kernel(
        const float* __restrict__ src, int src_bstride,
        float* __restrict__ dst, int dst_bstride,
        const float* __restrict__ Wm,
        const float* __restrict__ bias,
        const int* __restrict__ t, int s) {
    const int b    = blockIdx.y;
    const int tid  = threadIdx.x;
    const int lane = tid & 31;
    const int wid  = tid >> 5;
    const int chunk = wid & 3;
    const int grp   = wid >> 2;                 // 0 or 1
    const int y0    = blockIdx.x * 32 + grp * 16;
    const int slot  = s >> 1;

    const float* __restrict__ u = src + (size_t)b * src_bstride;
    float* __restrict__ v       = dst + (size_t)b * dst_bstride;

    const int xb  = chunk << 7;
    const int x4  = xb + (lane << 2);
    const int xl2 = (xb + WW - 2) & (WW - 1);   // cols xb-2, xb-1 (float2)
    const int xr2 = (xb + 128) & (WW - 1);      // cols xb+128, xb+129 (float2)

    // ---- Edge data for 20 rows (lanes 0..19), issued first ----
    float2 eL = make_float2(0.f, 0.f), eR = make_float2(0.f, 0.f);
    float sxb = 0.0f, sxbr = 0.0f;
    if (lane < 20) {
        const int row = ((y0 - 2 + lane) & (HH - 1)) << 9;
        eL   = *(const float2*)(u + row + xl2);   // (xb-2, xb-1)
        eR   = *(const float2*)(u + row + xr2);   // (xb+128, xb+129)
        sxb  = u[row + xb];                       // col xb
        sxbr = u[row + xb + 127];                 // col xb+127
    }

    // ---- Software-pipelined main-row loads: preload 5 of 20 ----
    float4 R[20];
    #pragma unroll
    for (int k = 0; k < 5; k++)
        R[k] = *(const float4*)(u + (((y0 - 2 + k) & (HH - 1)) << 9) + x4);

    // ---- D/rho for both sub-steps (overlaps loads) ----
    const float inv = 1.0f / (float)PLANE;
    const float sum_s = g_sum0[slot * BATCH + b];
    const float ssq_s = g_sumsq[slot * BATCH + b];
    const float f1 = g_sumc[0 * BATCH + b] * inv;
    const float f2 = g_sumc[1 * BATCH + b] * inv;
    const float f3 = g_sumc[2 * BATCH + b] * inv;
    const float zc0 = f1 * Wm[2] + f2 * Wm[4] + f3 * Wm[6] + bias[0];
    const float zc1 = f1 * Wm[3] + f2 * Wm[5] + f3 * Wm[7] + bias[1];
    const int tb = t[b];

    const float f0 = sum_s * inv;
    float D0 = D_SCALE   / (1.0f + __expf(-(f0 * Wm[0] + zc0)));
    float r0 = RHO_SCALE / (1.0f + __expf(-(f0 * Wm[1] + zc1)));
    if (tb <= s) { D0 = 0.0f; r0 = 0.0f; }

    const float sum_n = sum_s + r0 * (sum_s - ssq_s);   // exact (periodic BC)
    const float f0n = sum_n * inv;
    float D1 = D_SCALE   / (1.0f + __expf(-(f0n * Wm[0] + zc0)));
    float r1 = RHO_SCALE / (1.0f + __expf(-(f0n * Wm[1] + zc1)));
    if (tb <= s + 1) { D1 = 0.0f; r1 = 0.0f; }

    // ---- Edge intermediates: lane i = row y0-2+i (valid i=1..18) ----
    float iLv, iRv;
    {
        float up = __shfl_up_sync(FULLM, eL.y, 1);
        float dn = __shfl_down_sync(FULLM, eL.y, 1);
        iLv = fmaf(D0, up + dn + eL.x + sxb - 4.0f * eL.y,
                   fmaf(r0 * eL.y, 1.0f - eL.y, eL.y));
        up = __shfl_up_sync(FULLM, eR.x, 1);
        dn = __shfl_down_sync(FULLM, eR.x, 1);
        iRv = fmaf(D0, up + dn + sxbr + eR.y - 4.0f * eR.x,
                   fmaf(r0 * eR.x, 1.0f - eR.x, eR.x));
    }

    // ---- Main loop: intermediates m=0..17 (rows y0-1..y0+16), outputs j=m-2 ----
    float4 I[3];
    float acc = 0.0f, acc2 = 0.0f;
    #pragma unroll
    for (int m = 0; m < 18; m++) {
        if (m + 5 < 20)
            R[m + 5] = *(const float4*)(u + (((y0 + 3 + m) & (HH - 1)) << 9) + x4);

        const float4 P = R[m], C = R[m + 1], N = R[m + 2];
        const float lein = __shfl_sync(FULLM, eL.y, m + 1);
        const float riin = __shfl_sync(FULLM, eR.x, m + 1);
        float le = __shfl_up_sync(FULLM, C.w, 1);
        float ri = __shfl_down_sync(FULLM, C.x, 1);
        if (lane == 0)  le = lein;
        if (lane == 31) ri = riin;

        float4 o;
        o.x = fmaf(D0, P.x + N.x + le  + C.y - 4.0f * C.x, fmaf(r0 * C.x, 1.0f - C.x, C.x));
        o.y = fmaf(D0, P.y + N.y + C.x + C.z - 4.0f * C.y, fmaf(r0 * C.y, 1.0f - C.y, C.y));
        o.z = fmaf(D0, P.z + N.z + C.y + C.w - 4.0f * C.z, fmaf(r0 * C.z, 1.0f - C.z, C.z));
        o.w = fmaf(D0, P.w + N.w + C.z + ri  - 4.0f * C.w, fmaf(r0 * C.w, 1.0f - C.w, C.w));
        I[m % 3] = o;

        if (m >= 2) {
            const int j = m - 2;                      // output row y0+j
            const float4 Pm = I[j % 3];
            const float4 Cm = I[(j + 1) % 3];
            const float4 Nm = I[(j + 2) % 3];
            const float leo = __shfl_sync(FULLM, iLv, j + 2);
            const float rio = __shfl_sync(FULLM, iRv, j + 2);
            float le2 = __shfl_up_sync(FULLM, Cm.w, 1);
            float ri2 = __shfl_down_sync(FULLM, Cm.x, 1);
            if (lane == 0)  le2 = leo;
            if (lane == 31) ri2 = rio;

            float4 q;
            q.x = fmaf(D1, Pm.x + Nm.x + le2 + Cm.y - 4.0f * Cm.x, fmaf(r1 * Cm.x, 1.0f - Cm.x, Cm.x));
            q.y = fmaf(D1, Pm.y + Nm.y + Cm.x + Cm.z - 4.0f * Cm.y, fmaf(r1 * Cm.y, 1.0f - Cm.y, Cm.y));
            q.z = fmaf(D1, Pm.z + Nm.z + Cm.y + Cm.w - 4.0f * Cm.z, fmaf(r1 * Cm.z, 1.0f - Cm.z, Cm.z));
            q.w = fmaf(D1, Pm.w + Nm.w + Cm.z + ri2  - 4.0f * Cm.w, fmaf(r1 * Cm.w, 1.0f - Cm.w, Cm.w));

            float4* dstp = (float4*)(v + ((y0 + j) << 9) + x4);
            if (LAST) __stcs(dstp, q);    // out ch0: never re-read on-device
            else      *dstp = q;          // intermediate: next kernel reads it
            if (!LAST) {
                acc  += (q.x + q.y) + (q.z + q.w);
                acc2 += (q.x * q.x + q.y * q.y) + (q.z * q.z + q.w * q.w);
            }
        }
    }

    if (!LAST) {
        // ---- Block reduction of sum & sumsq, one atomic pair per block ----
        #pragma unroll
        for (int o = 16; o > 0; o >>= 1) {
            acc  += __shfl_down_sync(FULLM, acc,  o);
            acc2 += __shfl_down_sync(FULLM, acc2, o);
        }
        __shared__ float ws[8], ws2[8];
        if (lane == 0) { ws[wid] = acc; ws2[wid] = acc2; }
        __syncthreads();
        if (wid == 0) {
            acc  = (lane < 8) ? ws[lane]  : 0.0f;
            acc2 = (lane < 8) ? ws2[lane] : 0.0f;
            #pragma unroll
            for (int o = 4; o > 0; o >>= 1) {
                acc  += __shfl_down_sync(0x000000ffu, acc,  o);
                acc2 += __shfl_down_sync(0x000000ffu, acc2, o);
            }
            if (lane == 0) {
                atomicAdd(&g_sum0[(slot + 1) * BATCH + b],  acc);
                atomicAdd(&g_sumsq[(slot + 1) * BATCH + b], acc2);
            }
        }
    }
}

extern "C" void kernel_launch(void* const* d_in, const int* in_sizes, int n_in,
                              void* d_out, int out_size) {
    const float* x  = (const float*)d_in[0];   // (32,4,512,512)
    const float* Wm = (const float*)d_in[1];   // (4,2)
    const float* bb = (const float*)d_in[2];   // (2,)
    const int*   t  = (const int*)d_in[3];     // (32,)
    float* out = (float*)d_out;

    zero_sums_kernel<<<1, 256>>>();

    // Copy ch1..3 (streaming, MLP=4), reduce per-(b,c) sums (+ sumsq ch0).
    init_kernel<<<dim3(64, BATCH * NCH), dim3(256)>>>(x, out);

    float* bufA; float* bufB;
    cudaGetSymbolAddress((void**)&bufA, g_buf0);
    cudaGetSymbolAddress((void**)&bufB, g_buf1);

    const dim3 fgrid(HH / 32, BATCH);   // (16, 32) = 512 blocks, ~single wave
    for (int k = 0; k < 4; k++) {
        const int s = 2 * k;
        const float* src;  int sstride;
        float*       dst;  int dstride;
        if (k == 0) { src = x;  sstride = NCH * PLANE; }
        else        { src = (k & 1) ? bufA : bufB; sstride = PLANE; }
        if (k == 3) { dst = out; dstride = NCH * PLANE; }
        else        { dst = (k & 1) ? bufB : bufA; dstride = PLANE; }
        if (k < 3)
            fused2_kernel<false><<<fgrid, 256>>>(src, sstride, dst, dstride,
                                                 Wm, bb, t, s);
        else
            fused2_kernel<true ><<<fgrid, 256>>>(src, sstride, dst, dstride,
                                                 Wm, bb, t, s);
    }
}